// round 12
// baseline (speedup 1.0000x reference)
#include <cuda_runtime.h>
#include <cuda_bf16.h>
#include <cstdint>

// ODEHypernet2D: per-batch hypernetwork MLP, DIMS = [2,256,256,256,2]
// B=64, N=2048. Inputs: ctx[B,N], y[B,N,2], y_points[B,N,2], tnw[B,136716]. Out: [B,N,2] f32.
//
// Weight layout per batch (float offsets):
//   L0: W[4][256]   @0      bias@1024   ws@1280   bs@1536   sh@1792
//   L1: W[258][256] @2048   bias@68096  ws@68352  bs@68608  sh@68864
//   L2: W[258][256] @69120  bias@135168 ws@135424 bs@135680 sh@135936
//   L3: W[258][2]   @136192 bias@136708 ws@136710 bs@136712 sh@136714
//
// R11 evidence: fma=24.3%, L1=42.5%, occ=11.8%, issue=32% -> stall-bound.
// This version: 2 outputs/thread (FFMA2:LDS 4:1), TILE_N=32 with 2 CTAs/SM
// (16 warps/SM), 2-deep weight prefetch (256-cyc cover > 234-cyc L2 hit).

#define B_DIM      64
#define N_DIM      2048
#define TOTAL_W    136716
#define TILE_N     32
#define NPAD       36          // row pitch (floats): 144 B, 16B-aligned
#define KBIG       258
#define PT         16          // points per thread
#define PPAIR      (PT/2)      // 8 f32x2 accumulators per output
#define PQUAD      (PT/4)      // 4 LDS.128 per row per thread

// ---- packed fp32x2 helpers ----
__device__ __forceinline__ unsigned long long pack2(float lo, float hi) {
    unsigned long long r;
    asm("mov.b64 %0, {%1,%2};" : "=l"(r) : "f"(lo), "f"(hi));
    return r;
}
__device__ __forceinline__ void unpack2(unsigned long long v, float& lo, float& hi) {
    asm("mov.b64 {%0,%1}, %2;" : "=f"(lo), "=f"(hi) : "l"(v));
}
__device__ __forceinline__ void ffma2(unsigned long long& d,
                                      unsigned long long a,
                                      unsigned long long b) {
    asm("fma.rn.f32x2 %0, %1, %2, %0;" : "+l"(d) : "l"(a), "l"(b));
}

__device__ __forceinline__ float sigmoidf_(float x) {
    return 1.0f / (1.0f + expf(-x));
}
__device__ __forceinline__ float softplusf_(float x) {
    return fmaxf(x, 0.0f) + log1pf(expf(-fabsf(x)));
}

// One 256-wide layer. Thread handles outputs {o, o+128}, points [pg*16, pg*16+16).
template<int K, bool SOFTPLUS>
__device__ __forceinline__ void layer2x(const float* __restrict__ src,
                                        float* __restrict__ dst,
                                        const float* __restrict__ wb,
                                        int woff,
                                        const float* __restrict__ ctxs,
                                        int o, int pg)
{
    unsigned long long acc0[PPAIR], acc1[PPAIR];
    const unsigned long long z = pack2(0.0f, 0.0f);
#pragma unroll
    for (int p = 0; p < PPAIR; ++p) { acc0[p] = z; acc1[p] = z; }

    const float* __restrict__ Wl0 = wb + woff + o;
    const float* __restrict__ Wl1 = Wl0 + 128;
    const float* __restrict__ srow = src + pg * PT;

    // 2-deep weight prefetch pipeline
    float a0 = Wl0[0],               b0 = Wl1[0];
    float a1 = (K > 1) ? Wl0[256] : 0.0f;
    float b1 = (K > 1) ? Wl1[256] : 0.0f;

#pragma unroll 2
    for (int i = 0; i < K; ++i) {
        float an = (i + 2 < K) ? Wl0[(size_t)(i + 2) * 256] : 0.0f;
        float bn = (i + 2 < K) ? Wl1[(size_t)(i + 2) * 256] : 0.0f;
        unsigned long long w0 = pack2(a0, a0);
        unsigned long long w1 = pack2(b0, b0);
        const ulonglong2* __restrict__ arow =
            (const ulonglong2*)(srow + (size_t)i * NPAD);
#pragma unroll
        for (int q = 0; q < PQUAD; ++q) {
            ulonglong2 a4 = arow[q];                 // LDS.128 broadcast
            ffma2(acc0[2 * q],     a4.x, w0);
            ffma2(acc0[2 * q + 1], a4.y, w0);
            ffma2(acc1[2 * q],     a4.x, w1);
            ffma2(acc1[2 * q + 1], a4.y, w1);
        }
        a0 = a1; b0 = b1; a1 = an; b1 = bn;
    }

    const int base = woff + K * 256;
#pragma unroll
    for (int s = 0; s < 2; ++s) {
        const int oo = o + s * 128;
        unsigned long long* acc = s ? acc1 : acc0;
        float bias = wb[base + oo];
        float ws   = wb[base + 256 + oo];
        float bs   = wb[base + 512 + oo];
        float sh   = wb[base + 768 + oo];
        float* __restrict__ drow = dst + (size_t)oo * NPAD + pg * PT;
#pragma unroll
        for (int p = 0; p < PPAIR; ++p) {
            float v0, v1;
            unpack2(acc[p], v0, v1);
            float c0 = ctxs[pg * PT + 2 * p];
            float c1 = ctxs[pg * PT + 2 * p + 1];
            v0 = (v0 + bias) * sigmoidf_(fmaf(c0, ws, bs)) + c0 * sh;
            v1 = (v1 + bias) * sigmoidf_(fmaf(c1, ws, bs)) + c1 * sh;
            if (SOFTPLUS) { v0 = softplusf_(v0); v1 = softplusf_(v1); }
            *(float2*)(drow + 2 * p) = make_float2(v0, v1);
        }
    }
}

__global__ void __launch_bounds__(256, 2)
ode_hypernet_kernel(const float* __restrict__ ctx,
                    const float* __restrict__ y,
                    const float* __restrict__ yp,
                    const float* __restrict__ tnw,
                    float* __restrict__ out)
{
    extern __shared__ float smem[];
    float* buf0 = smem;                        // [258][NPAD]
    float* buf1 = smem + KBIG * NPAD;          // [258][NPAD]
    float* ctxs = smem + 2 * KBIG * NPAD;      // [TILE_N]

    const int b  = blockIdx.y;
    const int n0 = blockIdx.x * TILE_N;
    const int t  = threadIdx.x;
    const int o  = t & 127;                    // output column (and o+128)
    const int pg = t >> 7;                     // point group: 0 or 1

    const float* __restrict__ wb = tnw + (size_t)b * TOTAL_W;

    if (t < TILE_N) {
        size_t gi = (size_t)b * N_DIM + n0 + t;
        float2 yv  = ((const float2*)y)[gi];
        float2 ypv = ((const float2*)yp)[gi];
        ctxs[t] = ctx[gi];
        buf0[0 * NPAD + t] = yv.x;
        buf0[1 * NPAD + t] = yv.y;
        buf0[2 * NPAD + t] = ypv.x;
        buf0[3 * NPAD + t] = ypv.y;
        buf0[256 * NPAD + t] = ypv.x;   // concat rows for layer-2 input
        buf0[257 * NPAD + t] = ypv.y;
        buf1[256 * NPAD + t] = ypv.x;   // concat rows for layer-1/3 input
        buf1[257 * NPAD + t] = ypv.y;
    }
    __syncthreads();

    layer2x<4, true>(buf0, buf1, wb, 0, ctxs, o, pg);
    __syncthreads();
    layer2x<KBIG, true>(buf1, buf0, wb, 2048, ctxs, o, pg);
    __syncthreads();
    layer2x<KBIG, true>(buf0, buf1, wb, 69120, ctxs, o, pg);
    __syncthreads();

    // L3: 258 -> 2. Threads 0..31, one point each.
    if (t < TILE_N) {
        float a0 = 0.0f, a1 = 0.0f;
        const float* __restrict__ W3 = wb + 136192;
#pragma unroll 4
        for (int i = 0; i < KBIG; ++i) {
            float a = buf1[(size_t)i * NPAD + t];
            a0 = fmaf(a, W3[2 * i],     a0);
            a1 = fmaf(a, W3[2 * i + 1], a1);
        }
        float c   = ctxs[t];
        float b0  = wb[136708], b1  = wb[136709];
        float ws0 = wb[136710], ws1 = wb[136711];
        float bs0 = wb[136712], bs1 = wb[136713];
        float sh0 = wb[136714], sh1 = wb[136715];
        float v0 = (a0 + b0) * sigmoidf_(fmaf(c, ws0, bs0)) + c * sh0;
        float v1 = (a1 + b1) * sigmoidf_(fmaf(c, ws1, bs1)) + c * sh1;
        ((float2*)out)[(size_t)b * N_DIM + n0 + t] = make_float2(v0, v1);
    }
}

extern "C" void kernel_launch(void* const* d_in, const int* in_sizes, int n_in,
                              void* d_out, int out_size)
{
    const float* ctx = (const float*)d_in[0];
    const float* y   = (const float*)d_in[1];
    const float* yp  = (const float*)d_in[2];
    const float* tnw = (const float*)d_in[3];
    float* out = (float*)d_out;

    const int smem_bytes = (2 * KBIG * NPAD + TILE_N) * (int)sizeof(float); // 74,432 B
    cudaFuncSetAttribute(ode_hypernet_kernel,
                         cudaFuncAttributeMaxDynamicSharedMemorySize, smem_bytes);

    dim3 grid(N_DIM / TILE_N, B_DIM);   // (64, 64) = 4096 CTAs
    ode_hypernet_kernel<<<grid, 256, smem_bytes>>>(ctx, y, yp, tnw, out);
}